// round 5
// baseline (speedup 1.0000x reference)
#include <cuda_runtime.h>
#include <math.h>

// SE block: B=32, H=W=56 (HW=3136), C=256, R=16, fp32 NHWC.
// out = in * sigmoid(relu(mean_hw(in) @ W1 + b1) @ W2 + b2)
//
// L2 strategy: input (102.8 MB) fits in L2 (~126 MB). Pass 1 reads it with
// 256-bit ld.global.nc.L2::evict_last (pin); pass 3 re-reads it (L2 hits,
// evict_first) and streams the output with st.global.cs so writes don't
// displace the pinned input. DRAM traffic ~206 MB instead of ~308 MB.
// NOTE: sm_100 ptxas requires .v8.b32 for L2::evict_* load hints.

#define Bb      32
#define HW      3136
#define Cc      256
#define CR      16
#define KSPLIT  32          // spatial chunks per batch for the pool pass
#define CHUNK   98          // 3136 / 32
#define OQ      32          // C/8 "octs" (8 floats = 32 B) per position

__device__ float g_partial[Bb * KSPLIT * Cc];   // 1 MB scratch
__device__ float g_exc[Bb * Cc];                // 32 KB excitation

// ---- 256-bit cache-hinted loads (sm_100 requires v8.b32 for evict hints) ---
__device__ __forceinline__ void ldg256_evict_last(const float* p, float* v) {
    unsigned r0, r1, r2, r3, r4, r5, r6, r7;
    asm volatile("ld.global.nc.L2::evict_last.v8.b32 {%0,%1,%2,%3,%4,%5,%6,%7}, [%8];"
                 : "=r"(r0), "=r"(r1), "=r"(r2), "=r"(r3),
                   "=r"(r4), "=r"(r5), "=r"(r6), "=r"(r7)
                 : "l"(p));
    v[0] = __uint_as_float(r0); v[1] = __uint_as_float(r1);
    v[2] = __uint_as_float(r2); v[3] = __uint_as_float(r3);
    v[4] = __uint_as_float(r4); v[5] = __uint_as_float(r5);
    v[6] = __uint_as_float(r6); v[7] = __uint_as_float(r7);
}
__device__ __forceinline__ void ldg256_evict_first(const float* p, float* v) {
    unsigned r0, r1, r2, r3, r4, r5, r6, r7;
    asm volatile("ld.global.nc.L2::evict_first.v8.b32 {%0,%1,%2,%3,%4,%5,%6,%7}, [%8];"
                 : "=r"(r0), "=r"(r1), "=r"(r2), "=r"(r3),
                   "=r"(r4), "=r"(r5), "=r"(r6), "=r"(r7)
                 : "l"(p));
    v[0] = __uint_as_float(r0); v[1] = __uint_as_float(r1);
    v[2] = __uint_as_float(r2); v[3] = __uint_as_float(r3);
    v[4] = __uint_as_float(r4); v[5] = __uint_as_float(r5);
    v[6] = __uint_as_float(r6); v[7] = __uint_as_float(r7);
}
__device__ __forceinline__ void stg128_streaming(float* p, const float* v) {
    asm volatile("st.global.cs.v4.f32 [%0], {%1,%2,%3,%4};"
                 :: "l"(p), "f"(v[0]), "f"(v[1]), "f"(v[2]), "f"(v[3]) : "memory");
}

// ---------------------------------------------------------------------------
// Pass 1: partial spatial sums, input pinned into L2 (evict_last).
// grid = B*KSPLIT blocks, 256 threads. q = tid&31 -> 32B channel oct,
// pg = tid>>5 -> one of 8 position sub-streams. 256 threads cover 8 full
// spatial positions (8 KB) per iteration, fully coalesced.
// ---------------------------------------------------------------------------
__global__ void __launch_bounds__(256) se_pool_partial(const float* __restrict__ in)
{
    const int b   = blockIdx.x / KSPLIT;
    const int k   = blockIdx.x % KSPLIT;
    const int tid = threadIdx.x;
    const int q   = tid & 31;
    const int pg  = tid >> 5;

    const float* __restrict__ base = in + (size_t)b * HW * Cc;

    float acc[8] = {0.f, 0.f, 0.f, 0.f, 0.f, 0.f, 0.f, 0.f};
    const int pEnd = (k + 1) * CHUNK;
    #pragma unroll 2
    for (int p = k * CHUNK + pg; p < pEnd; p += 8) {
        float v[8];
        ldg256_evict_last(base + (size_t)p * Cc + q * 8, v);
        #pragma unroll
        for (int j = 0; j < 8; j++) acc[j] += v[j];
    }

    __shared__ float s[256][8];
    #pragma unroll
    for (int j = 0; j < 8; j++) s[tid][j] = acc[j];
    __syncthreads();

    // threads 0..31 reduce the 8 position sub-streams for their oct
    if (tid < 32) {
        float r[8];
        #pragma unroll
        for (int j = 0; j < 8; j++) r[j] = s[tid][j];
        #pragma unroll
        for (int g = 1; g < 8; g++)
            #pragma unroll
            for (int j = 0; j < 8; j++) r[j] += s[g * 32 + tid][j];
        float* dst = g_partial + ((b * KSPLIT + k) * Cc + tid * 8);
        #pragma unroll
        for (int j = 0; j < 8; j++) dst[j] = r[j];
    }
}

// ---------------------------------------------------------------------------
// Pass 2: finish mean, tiny MLP (256 -> 16 relu -> 256 sigmoid). grid = B.
// ---------------------------------------------------------------------------
__global__ void __launch_bounds__(256) se_excite(const float* __restrict__ W1,
                                                 const float* __restrict__ b1,
                                                 const float* __restrict__ W2,
                                                 const float* __restrict__ b2)
{
    const int b = blockIdx.x;
    const int c = threadIdx.x;

    __shared__ float sq[Cc];
    __shared__ float hs[CR];

    float sum = 0.f;
    #pragma unroll
    for (int k = 0; k < KSPLIT; k++)
        sum += g_partial[(b * KSPLIT + k) * Cc + c];
    sq[c] = sum * (1.0f / (float)HW);
    __syncthreads();

    if (c < CR) {
        float h = b1[c];
        #pragma unroll 8
        for (int i = 0; i < Cc; i++)
            h = fmaf(sq[i], W1[i * CR + c], h);
        hs[c] = fmaxf(h, 0.f);
    }
    __syncthreads();

    float e = b2[c];
    #pragma unroll
    for (int j = 0; j < CR; j++)
        e = fmaf(hs[j], W2[j * Cc + c], e);
    g_exc[b * Cc + c] = 1.0f / (1.0f + __expf(-e));
}

// ---------------------------------------------------------------------------
// Pass 3: out = in * exc[b,c]. Input reads hit the pinned L2 lines
// (evict_first: done with them after this read); output streams past L2
// (st.global.cs). 2D grid: y = batch, x covers HW*OQ octs.
// ---------------------------------------------------------------------------
__global__ void __launch_bounds__(256) se_scale(const float* __restrict__ in,
                                                float* __restrict__ out)
{
    const int b = blockIdx.y;
    const float* __restrict__ inb  = in  + (size_t)b * HW * Cc;
    float* __restrict__       outb = out + (size_t)b * HW * Cc;

    const int total  = HW * OQ;                       // 100352 octs per batch
    const int stride = gridDim.x * blockDim.x;        // 18944, multiple of 32

    // Per-thread excitation oct: (i & 31) is invariant across the loop.
    const int q = threadIdx.x & 31;
    float e[8];
    {
        const float4* e4 = reinterpret_cast<const float4*>(g_exc + b * Cc + q * 8);
        float4 e0 = __ldg(&e4[0]);
        float4 e1 = __ldg(&e4[1]);
        e[0] = e0.x; e[1] = e0.y; e[2] = e0.z; e[3] = e0.w;
        e[4] = e1.x; e[5] = e1.y; e[6] = e1.z; e[7] = e1.w;
    }

    for (int i = blockIdx.x * blockDim.x + threadIdx.x; i < total; i += stride) {
        float v[8];
        ldg256_evict_first(inb + (size_t)i * 8, v);
        #pragma unroll
        for (int j = 0; j < 8; j++) v[j] *= e[j];
        stg128_streaming(outb + (size_t)i * 8,     v);
        stg128_streaming(outb + (size_t)i * 8 + 4, v + 4);
    }
}

// ---------------------------------------------------------------------------
extern "C" void kernel_launch(void* const* d_in, const int* in_sizes, int n_in,
                              void* d_out, int out_size)
{
    const float* in = (const float*)d_in[0];
    const float* W1 = (const float*)d_in[1];
    const float* b1 = (const float*)d_in[2];
    const float* W2 = (const float*)d_in[3];
    const float* b2 = (const float*)d_in[4];
    float* out = (float*)d_out;

    se_pool_partial<<<Bb * KSPLIT, 256>>>(in);
    se_excite<<<Bb, 256>>>(W1, b1, W2, b2);
    se_scale<<<dim3(74, Bb), 256>>>(in, out);   // 2368 blocks, 16 waves
}

// round 6
// speedup vs baseline: 1.1042x; 1.1042x over previous
#include <cuda_runtime.h>
#include <math.h>

// SE block: B=32, H=W=56 (HW=3136), C=256, R=16, fp32 NHWC.
// out = in * sigmoid(relu(mean_hw(in) @ W1 + b1) @ W2 + b2)
//
// R5: maximize MLP with plain 128-bit accesses (L2 hints are a non-lever:
// LTS cap is path-independent). Pool: 4 independent loads in flight, no tail.
// Scale: 8 independent loads in flight per thread, exact cover, no loop.

#define Bb      32
#define HW      3136
#define Cc      256
#define CR      16
#define KSPLIT  28          // spatial chunks per batch (pool pass)
#define CHUNK   112         // 3136 / 28
#define CQ      64          // C/4 float4 quads per position

__device__ float g_partial[Bb * KSPLIT * Cc];   // 896 KB scratch
__device__ float g_exc[Bb * Cc];                // 32 KB excitation

// ---------------------------------------------------------------------------
// Pass 1: partial spatial sums. grid = B*KSPLIT = 896 blocks, 256 threads.
// q = tid&63 -> channel quad, pg = tid>>6 -> one of 4 position sub-streams.
// Each pg-stream covers positions p0 + 4t, t = 0..27; unrolled 4-wide into
// 4 independent accumulators -> 4 LDG.128 in flight, 7 iterations, no tail.
// ---------------------------------------------------------------------------
__global__ void __launch_bounds__(256) se_pool_partial(const float* __restrict__ in)
{
    const int b   = blockIdx.x / KSPLIT;
    const int k   = blockIdx.x % KSPLIT;
    const int tid = threadIdx.x;
    const int q   = tid & 63;
    const int pg  = tid >> 6;

    const float4* __restrict__ in4 = reinterpret_cast<const float4*>(in)
                                     + (size_t)b * HW * CQ
                                     + (size_t)(k * CHUNK + pg) * CQ + q;

    float4 a0 = make_float4(0.f, 0.f, 0.f, 0.f);
    float4 a1 = a0, a2 = a0, a3 = a0;

    #pragma unroll
    for (int t = 0; t < CHUNK / 4; t += 4) {           // 7 iterations
        float4 v0 = __ldg(in4 + (size_t)(4 * (t + 0)) * CQ);
        float4 v1 = __ldg(in4 + (size_t)(4 * (t + 1)) * CQ);
        float4 v2 = __ldg(in4 + (size_t)(4 * (t + 2)) * CQ);
        float4 v3 = __ldg(in4 + (size_t)(4 * (t + 3)) * CQ);
        a0.x += v0.x; a0.y += v0.y; a0.z += v0.z; a0.w += v0.w;
        a1.x += v1.x; a1.y += v1.y; a1.z += v1.z; a1.w += v1.w;
        a2.x += v2.x; a2.y += v2.y; a2.z += v2.z; a2.w += v2.w;
        a3.x += v3.x; a3.y += v3.y; a3.z += v3.z; a3.w += v3.w;
    }
    a0.x += a1.x + a2.x + a3.x;
    a0.y += a1.y + a2.y + a3.y;
    a0.z += a1.z + a2.z + a3.z;
    a0.w += a1.w + a2.w + a3.w;

    __shared__ float4 s[256];
    s[tid] = a0;
    __syncthreads();

    if (tid < 64) {
        float4 a = s[tid];
        float4 c = s[tid + 64];
        float4 d = s[tid + 128];
        float4 e = s[tid + 192];
        float4 r = make_float4(a.x + c.x + d.x + e.x,
                               a.y + c.y + d.y + e.y,
                               a.z + c.z + d.z + e.z,
                               a.w + c.w + d.w + e.w);
        reinterpret_cast<float4*>(g_partial)[(blockIdx.x) * CQ + tid] = r;
    }
}

// ---------------------------------------------------------------------------
// Pass 2: finish mean, tiny MLP (256 -> 16 relu -> 256 sigmoid). grid = B.
// ---------------------------------------------------------------------------
__global__ void __launch_bounds__(256) se_excite(const float* __restrict__ W1,
                                                 const float* __restrict__ b1,
                                                 const float* __restrict__ W2,
                                                 const float* __restrict__ b2)
{
    const int b = blockIdx.x;
    const int c = threadIdx.x;

    __shared__ float sq[Cc];
    __shared__ float hs[CR];

    float sum = 0.f;
    #pragma unroll
    for (int k = 0; k < KSPLIT; k++)
        sum += g_partial[(b * KSPLIT + k) * Cc + c];
    sq[c] = sum * (1.0f / (float)HW);
    __syncthreads();

    if (c < CR) {
        float h = b1[c];
        #pragma unroll 8
        for (int i = 0; i < Cc; i++)
            h = fmaf(sq[i], W1[i * CR + c], h);
        hs[c] = fmaxf(h, 0.f);
    }
    __syncthreads();

    float e = b2[c];
    #pragma unroll
    for (int j = 0; j < CR; j++)
        e = fmaf(hs[j], W2[j * Cc + c], e);
    g_exc[b * Cc + c] = 1.0f / (1.0f + __expf(-e));
}

// ---------------------------------------------------------------------------
// Pass 3: out = in * exc[b,c]. Exact cover: grid (98, 32) x 256 threads,
// each thread handles 8 quads at stride 25088 (98*256). 25088 % 64 == 0, so
// (index & 63) is invariant -> one excitation quad per thread. 8 independent
// LDG.128 in flight, then 8 STG.128.
// ---------------------------------------------------------------------------
#define SBLK 98
#define SSTRIDE (SBLK * 256)   // 25088 quads

__global__ void __launch_bounds__(256) se_scale(const float* __restrict__ in,
                                                float* __restrict__ out)
{
    const int b  = blockIdx.y;
    const int i0 = blockIdx.x * 256 + threadIdx.x;

    const float4* __restrict__ in4  = reinterpret_cast<const float4*>(in)
                                      + (size_t)b * HW * CQ;
    float4* __restrict__       out4 = reinterpret_cast<float4*>(out)
                                      + (size_t)b * HW * CQ;

    const float4 e = __ldg(reinterpret_cast<const float4*>(g_exc)
                           + b * CQ + (threadIdx.x & 63));

    float4 v[8];
    #pragma unroll
    for (int m = 0; m < 8; m++)
        v[m] = __ldg(in4 + i0 + m * SSTRIDE);

    #pragma unroll
    for (int m = 0; m < 8; m++) {
        v[m].x *= e.x; v[m].y *= e.y; v[m].z *= e.z; v[m].w *= e.w;
        out4[i0 + m * SSTRIDE] = v[m];
    }
}

// ---------------------------------------------------------------------------
extern "C" void kernel_launch(void* const* d_in, const int* in_sizes, int n_in,
                              void* d_out, int out_size)
{
    const float* in = (const float*)d_in[0];
    const float* W1 = (const float*)d_in[1];
    const float* b1 = (const float*)d_in[2];
    const float* W2 = (const float*)d_in[3];
    const float* b2 = (const float*)d_in[4];
    float* out = (float*)d_out;

    se_pool_partial<<<Bb * KSPLIT, 256>>>(in);      // 896 blocks
    se_excite<<<Bb, 256>>>(W1, b1, W2, b2);
    se_scale<<<dim3(SBLK, Bb), 256>>>(in, out);     // 3136 blocks, exact cover
}

// round 7
// speedup vs baseline: 1.2089x; 1.0949x over previous
#include <cuda_runtime.h>
#include <math.h>

// SE block: B=32, H=W=56 (HW=3136), C=256, R=16, fp32 NHWC.
// out = in * sigmoid(relu(mean_hw(in) @ W1 + b1) @ W2 + b2)
//
// R6: (a) pool grid = 1184 = 8 blocks x 148 SMs exactly (one full wave,
// occupancy ~100%); (b) scale writes with st.global.cs (evict-first) so the
// output stream doesn't evict the L2-resident input that pool just read,
// and traverses in reverse pool order to align reuse with LRU recency.

#define Bb      32
#define HW      3136
#define Cc      256
#define CR      16
#define KSPLIT  37          // 32*37 = 1184 blocks = 8 per SM on 148 SMs
#define CHUNKP  85          // ceil(3136/37); last chunk is 76
#define CQ      64          // C/4 float4 quads per position

__device__ float g_partial[Bb * KSPLIT * Cc];   // ~1.2 MB scratch
__device__ float g_exc[Bb * Cc];                // 32 KB excitation

__device__ __forceinline__ void stg_cs(float4* p, float4 v) {
    asm volatile("st.global.cs.v4.f32 [%0], {%1,%2,%3,%4};"
                 :: "l"(p), "f"(v.x), "f"(v.y), "f"(v.z), "f"(v.w) : "memory");
}

// ---------------------------------------------------------------------------
// Pass 1: partial spatial sums. grid = B*KSPLIT = 1184 blocks, 256 threads.
// q = tid&63 -> channel quad, pg = tid>>6 -> one of 4 position sub-streams.
// R2's proven 32-reg loop body (2-deep software pipeline), ragged chunk tail.
// ---------------------------------------------------------------------------
__global__ void __launch_bounds__(256) se_pool_partial(const float* __restrict__ in)
{
    const int b   = blockIdx.x / KSPLIT;
    const int k   = blockIdx.x % KSPLIT;
    const int tid = threadIdx.x;
    const int q   = tid & 63;
    const int pg  = tid >> 6;

    const float4* __restrict__ in4 = reinterpret_cast<const float4*>(in)
                                     + (size_t)b * HW * CQ;

    float4 a0 = make_float4(0.f, 0.f, 0.f, 0.f);
    float4 a1 = make_float4(0.f, 0.f, 0.f, 0.f);
    const int pBeg = k * CHUNKP;
    const int pEnd = (pBeg + CHUNKP < HW) ? (pBeg + CHUNKP) : HW;
    int p = pBeg + pg;
    for (; p + 4 < pEnd; p += 8) {
        float4 v0 = __ldg(&in4[(size_t)p * CQ + q]);
        float4 v1 = __ldg(&in4[(size_t)(p + 4) * CQ + q]);
        a0.x += v0.x; a0.y += v0.y; a0.z += v0.z; a0.w += v0.w;
        a1.x += v1.x; a1.y += v1.y; a1.z += v1.z; a1.w += v1.w;
    }
    if (p < pEnd) {
        float4 v0 = __ldg(&in4[(size_t)p * CQ + q]);
        a0.x += v0.x; a0.y += v0.y; a0.z += v0.z; a0.w += v0.w;
    }
    a0.x += a1.x; a0.y += a1.y; a0.z += a1.z; a0.w += a1.w;

    __shared__ float4 s[256];
    s[tid] = a0;
    __syncthreads();

    if (tid < 64) {
        float4 a = s[tid];
        float4 c = s[tid + 64];
        float4 d = s[tid + 128];
        float4 e = s[tid + 192];
        float4 r = make_float4(a.x + c.x + d.x + e.x,
                               a.y + c.y + d.y + e.y,
                               a.z + c.z + d.z + e.z,
                               a.w + c.w + d.w + e.w);
        reinterpret_cast<float4*>(g_partial)[blockIdx.x * CQ + tid] = r;
    }
}

// ---------------------------------------------------------------------------
// Pass 2: finish mean, tiny MLP (256 -> 16 relu -> 256 sigmoid). grid = B.
// ---------------------------------------------------------------------------
__global__ void __launch_bounds__(256) se_excite(const float* __restrict__ W1,
                                                 const float* __restrict__ b1,
                                                 const float* __restrict__ W2,
                                                 const float* __restrict__ b2)
{
    const int b = blockIdx.x;
    const int c = threadIdx.x;

    __shared__ float sq[Cc];
    __shared__ float hs[CR];

    float sum = 0.f;
    #pragma unroll
    for (int k = 0; k < KSPLIT; k++)
        sum += g_partial[(b * KSPLIT + k) * Cc + c];
    sq[c] = sum * (1.0f / (float)HW);
    __syncthreads();

    if (c < CR) {
        float h = b1[c];
        #pragma unroll 8
        for (int i = 0; i < Cc; i++)
            h = fmaf(sq[i], W1[i * CR + c], h);
        hs[c] = fmaxf(h, 0.f);
    }
    __syncthreads();

    float e = b2[c];
    #pragma unroll
    for (int j = 0; j < CR; j++)
        e = fmaf(hs[j], W2[j * Cc + c], e);
    g_exc[b * Cc + c] = 1.0f / (1.0f + __expf(-e));
}

// ---------------------------------------------------------------------------
// Pass 3: out = in * exc[b,c]. Exact cover: grid (98, 32) x 256 threads,
// 8 quads/thread at stride 25088 (== 0 mod 64 -> excitation quad invariant).
// Reads via plain __ldg (want L2 hits on pool-resident lines); writes via
// st.global.cs (evict-first) so the output stream doesn't flush the input.
// Block indices reversed so the most-recently-pooled data is read first.
// ---------------------------------------------------------------------------
#define SBLK 98
#define SSTRIDE (SBLK * 256)   // 25088 quads

__global__ void __launch_bounds__(256) se_scale(const float* __restrict__ in,
                                                float* __restrict__ out)
{
    const int b  = (Bb - 1)   - blockIdx.y;     // reverse batch order
    const int bx = (SBLK - 1) - blockIdx.x;     // reverse chunk order
    const int i0 = bx * 256 + threadIdx.x;

    const float4* __restrict__ in4  = reinterpret_cast<const float4*>(in)
                                      + (size_t)b * HW * CQ;
    float4* __restrict__       out4 = reinterpret_cast<float4*>(out)
                                      + (size_t)b * HW * CQ;

    const float4 e = __ldg(reinterpret_cast<const float4*>(g_exc)
                           + b * CQ + (threadIdx.x & 63));

    float4 v[8];
    #pragma unroll
    for (int m = 0; m < 8; m++)
        v[m] = __ldg(in4 + i0 + m * SSTRIDE);

    #pragma unroll
    for (int m = 0; m < 8; m++) {
        v[m].x *= e.x; v[m].y *= e.y; v[m].z *= e.z; v[m].w *= e.w;
        stg_cs(out4 + i0 + m * SSTRIDE, v[m]);
    }
}

// ---------------------------------------------------------------------------
extern "C" void kernel_launch(void* const* d_in, const int* in_sizes, int n_in,
                              void* d_out, int out_size)
{
    const float* in = (const float*)d_in[0];
    const float* W1 = (const float*)d_in[1];
    const float* b1 = (const float*)d_in[2];
    const float* W2 = (const float*)d_in[3];
    const float* b2 = (const float*)d_in[4];
    float* out = (float*)d_out;

    se_pool_partial<<<Bb * KSPLIT, 256>>>(in);      // 1184 blocks, 1 full wave
    se_excite<<<Bb, 256>>>(W1, b1, W2, b2);
    se_scale<<<dim3(SBLK, Bb), 256>>>(in, out);     // 3136 blocks
}